// round 6
// baseline (speedup 1.0000x reference)
#include <cuda_runtime.h>

// CenterLoss collapses: mask is one-hot on labels, so only distmat[i, labels[i]]
// survives; the other (B*C - B) masked zeros each clamp to 1e-12 (a constant).
// loss = ( sum_i clamp(||x_i - c_{labels[i]}||^2, 1e-12, 1e12) + (B*C-B)*1e-12 ) / B
//
// R6: single node (R5 structure) + tail trims:
//  - 64 blocks x 512 threads (same 1024 warps, half the same-address atomics)
//  - x load hoisted ahead of the label-dependent center gather
//  - finalize folded to one DP fma + store
// Count packed in bits [57,64) of the same u64 as the 2^32 fixed-point sum:
// the block whose atomicAdd RETURN carries count NBLK-1 owns the full sum.
// Exact integer accumulation => deterministic, fence-free.

#define BATCH     1024
#define NUM_CLASS 100000
#define FEAT      128

#define NBLK   64           // 64 blocks * 16 warps = 1024 warps = 1 per row
#define NWARP  16
#define CNT_SHIFT 57        // count bits [57,64); sum bits [0,57)
#define SUM_MASK  ((1ULL << CNT_SHIFT) - 1ULL)

__device__ unsigned long long g_acc = 0ULL;   // {count, fixed-point sum}

__global__ void __launch_bounds__(512)
center_loss_onepass(const float* __restrict__ x,
                    const int*   __restrict__ labels,
                    const float* __restrict__ centers,
                    float*       __restrict__ out) {
    const int warp = threadIdx.x >> 5;
    const int lane = threadIdx.x & 31;
    const int row  = blockIdx.x * NWARP + warp;   // 0..1023

    // issue the label-independent x load first, then the gather chain
    const float4 a = reinterpret_cast<const float4*>(x + (size_t)row * FEAT)[lane];
    const int  lab = labels[row];
    const float4 b = reinterpret_cast<const float4*>(centers + (size_t)lab * FEAT)[lane];

    const float d0 = a.x - b.x;
    const float d1 = a.y - b.y;
    const float d2 = a.z - b.z;
    const float d3 = a.w - b.w;
    float s = d0 * d0 + d1 * d1 + d2 * d2 + d3 * d3;

    // warp reduce -> full ||x - c||^2 for this row
    #pragma unroll
    for (int off = 16; off; off >>= 1)
        s += __shfl_xor_sync(0xffffffffu, s, off);

    // clamp (matches jnp.clip on the surviving diagonal entry)
    s = fminf(fmaxf(s, 1e-12f), 1e12f);

    // deterministic block reduce over the 16 warps (fixed order)
    __shared__ float sm[NWARP];
    if (lane == 0) sm[warp] = s;
    __syncthreads();

    if (threadIdx.x == 0) {
        float t = 0.0f;
        #pragma unroll
        for (int i = 0; i < NWARP; i++) t += sm[i];

        // exact fixed-point contribution + count tick in one atomic
        const unsigned long long fix =
            (unsigned long long)((double)t * 4294967296.0);      // * 2^32
        const unsigned long long packed = fix | (1ULL << CNT_SHIFT);
        const unsigned long long prev = atomicAdd(&g_acc, packed);

        if ((prev >> CNT_SHIFT) == (unsigned long long)(NBLK - 1)) {
            // last block: prev low bits + our contribution = exact total
            const unsigned long long total = (prev + packed) & SUM_MASK;
            // loss = total/2^32/B + (B*C-B)*1e-12/B, all constants folded
            const double SCALE = 1.0 / (4294967296.0 * (double)BATCH);
            const double BIAS  = ((double)NUM_CLASS - 1.0) * 1e-12;
            out[0] = (float)(fma((double)total, SCALE, BIAS));
            atomicExch(&g_acc, 0ULL);   // reset for next graph replay
        }
    }
}

extern "C" void kernel_launch(void* const* d_in, const int* in_sizes, int n_in,
                              void* d_out, int out_size) {
    const float* x       = (const float*)d_in[0];
    const int*   labels  = (const int*)  d_in[1];
    const float* centers = (const float*)d_in[2];
    float*       out     = (float*)d_out;

    center_loss_onepass<<<NBLK, 512>>>(x, labels, centers, out);
}